// round 12
// baseline (speedup 1.0000x reference)
#include <cuda_runtime.h>
#include <cstdint>

typedef unsigned long long ull;

#define HD 128
#define DD 256

// ---------- packed f32x2 helpers (Blackwell sm_100+) ----------
__device__ __forceinline__ void fma2(ull &d, ull a, ull b) {
    asm("fma.rn.f32x2 %0, %1, %2, %0;" : "+l"(d) : "l"(a), "l"(b));
}
__device__ __forceinline__ ull add2(ull a, ull b) {
    ull d; asm("add.rn.f32x2 %0, %1, %2;" : "=l"(d) : "l"(a), "l"(b)); return d;
}
__device__ __forceinline__ float2 unpack2(ull u) {
    float2 r; asm("mov.b64 {%0, %1}, %2;" : "=f"(r.x), "=f"(r.y) : "l"(u)); return r;
}
__device__ __forceinline__ ull pack2(float lo, float hi) {
    ull d; asm("mov.b64 %0, {%1, %2};" : "=l"(d) : "f"(lo), "f"(hi)); return d;
}
__device__ __forceinline__ float tanh_approx(float x) {
    float r; asm("tanh.approx.f32 %0, %1;" : "=f"(r) : "f"(x)); return r;
}

// ---------- Kernel 1: xW = input @ Wi^T + bi, written into out[S,128] ----------
__global__ void __launch_bounds__(128) gemm_xw_kernel(
    const float* __restrict__ X,   // [S, 256]
    const float* __restrict__ Wi,  // [128, 256]
    const float* __restrict__ bi,  // [128]
    float* __restrict__ out, int S)
{
    __shared__ __align__(16) float xs[32][DD];
    const int h  = threadIdx.x;
    const int s0 = blockIdx.x * 32;

    const float4* Xg  = (const float4*)(X + (size_t)s0 * DD);
    float4*       xs4 = (float4*)&xs[0][0];
#pragma unroll
    for (int i = 0; i < 16; i++) xs4[h + 128 * i] = Xg[h + 128 * i];
    __syncthreads();

    float acc[32];
#pragma unroll
    for (int s = 0; s < 32; s++) acc[s] = 0.f;

    const float4* wr = (const float4*)(Wi + h * DD);
#pragma unroll 4
    for (int kk = 0; kk < DD / 4; kk++) {
        float4 wv = wr[kk];
#pragma unroll
        for (int s = 0; s < 32; s++) {
            float4 xv = *(const float4*)&xs[s][kk * 4];
            acc[s] = fmaf(wv.x, xv.x, acc[s]);
            acc[s] = fmaf(wv.y, xv.y, acc[s]);
            acc[s] = fmaf(wv.z, xv.z, acc[s]);
            acc[s] = fmaf(wv.w, xv.w, acc[s]);
        }
    }
    const float b = bi[h];
#pragma unroll
    for (int s = 0; s < 32; s++) out[(size_t)(s0 + s) * HD + h] = acc[s] + b;
}

// ---------- Kernel 2: sequential recurrence ----------
// 128 threads = 4 warps (1/SMSP). Lane j owns output j; full Wh row j in
// registers, PRE-ROTATED so register group g <-> K-group (2*wrp+g)&7
// (groups 0,1 = this warp's own 32-float segment). Per step: STS h ->
// __syncthreads (sole ordering; no warp-forwarding assumptions) -> all
// loads issue post-bar (foreign groups 2,3 first, then own segment), FMAs
// run foreign groups 2..7 with depth-2 lookahead, OWN groups LAST (their
// LDS latency fully hidden under ~144 cyc of foreign FMA issue). 4-acc
// round-robin everywhere (R11 showed 2-chain phases regress). MUFU tanh;
// gmem h stores batched outside the inner loop; xw prefetched 8 ahead.
__global__ void __launch_bounds__(128, 1) rnn_seq_kernel(
    const float* __restrict__ Wh,  // [128, 128]
    const float* __restrict__ bh,  // [128]
    const float* __restrict__ h0,  // [1, 128]
    float* out,                    // [S, 128]: xw in, h out
    float* hn, int S, int has_hn)
{
    __shared__ __align__(16) float sh[2][HD];
    const int j   = threadIdx.x;
    const int wrp = j >> 5;

    // pre-rotated weights: register group g <-> K-group (2*wrp+g)&7
    ull w[64];
#pragma unroll
    for (int g = 0; g < 8; g++) {
        const int kg = (2 * wrp + g) & 7;
        const ulonglong2* wp = (const ulonglong2*)(Wh + j * HD + kg * 16);
#pragma unroll
        for (int u = 0; u < 4; u++) {
            ulonglong2 v = wp[u];
            w[8 * g + 2 * u]     = v.x;
            w[8 * g + 2 * u + 1] = v.y;
        }
    }
    const float bj = bh[j];

    sh[0][j] = h0[j];

    float xwb[8], xwn[8], hv[8];
#pragma unroll
    for (int q = 0; q < 8; q++) xwb[q] = out[q * HD + j] + bj;

    __syncthreads();

    for (int t = 0; t < S; t += 8) {
        // prefetch the next 8 xw rows (consumed next outer iteration)
#pragma unroll
        for (int q = 0; q < 8; q++) {
            int tn = t + 8 + q;
            xwn[q] = (tn < S) ? out[(size_t)tn * HD + j] : 0.f;
        }
#pragma unroll
        for (int q = 0; q < 8; q++) {
            const int buf  = q & 1;        // t % 8 == 0, so step parity == q parity
            const int nbuf = buf ^ 1;
            const float* hb = &sh[buf][0];

            // post-bar loads: foreign groups 2,3 first (consumed first),
            // then own segment (groups 0,1; consumed last)
            const ulonglong2* g2p = (const ulonglong2*)(hb + (((2*wrp + 2) & 7) << 4));
            const ulonglong2* g3p = (const ulonglong2*)(hb + (((2*wrp + 3) & 7) << 4));
            ulonglong2 A0 = g2p[0], A1 = g2p[1], A2 = g2p[2], A3 = g2p[3];
            ulonglong2 B0 = g3p[0], B1 = g3p[1], B2 = g3p[2], B3 = g3p[3];

            const ulonglong2* op = (const ulonglong2*)(hb + wrp * 32);
            ulonglong2 O0 = op[0], O1 = op[1], O2 = op[2], O3 = op[3];
            ulonglong2 O4 = op[4], O5 = op[5], O6 = op[6], O7 = op[7];

            // a0 seeded with (xw + bias); 4-acc round-robin throughout
            ull a0 = pack2(xwb[q], 0.0f);
            ull a1 = 0, a2 = 0, a3 = 0;

            // foreign groups 2..7, depth-2 lookahead
#pragma unroll
            for (int g = 2; g < 8; g++) {
                ulonglong2 N0, N1, N2, N3;
                if (g < 6) {
                    const ulonglong2* np = (const ulonglong2*)(hb + (((2*wrp + g + 2) & 7) << 4));
                    N0 = np[0]; N1 = np[1]; N2 = np[2]; N3 = np[3];
                }
                fma2(a0, w[8*g + 0], A0.x);
                fma2(a1, w[8*g + 1], A0.y);
                fma2(a2, w[8*g + 2], A1.x);
                fma2(a3, w[8*g + 3], A1.y);
                fma2(a0, w[8*g + 4], A2.x);
                fma2(a1, w[8*g + 5], A2.y);
                fma2(a2, w[8*g + 6], A3.x);
                fma2(a3, w[8*g + 7], A3.y);
                A0 = B0; A1 = B1; A2 = B2; A3 = B3;
                if (g < 6) { B0 = N0; B1 = N1; B2 = N2; B3 = N3; }
            }
            // own groups 0,1 LAST (data long since landed)
            fma2(a0, w[ 0], O0.x);  fma2(a1, w[ 1], O0.y);
            fma2(a2, w[ 2], O1.x);  fma2(a3, w[ 3], O1.y);
            fma2(a0, w[ 4], O2.x);  fma2(a1, w[ 5], O2.y);
            fma2(a2, w[ 6], O3.x);  fma2(a3, w[ 7], O3.y);
            fma2(a0, w[ 8], O4.x);  fma2(a1, w[ 9], O4.y);
            fma2(a2, w[10], O5.x);  fma2(a3, w[11], O5.y);
            fma2(a0, w[12], O6.x);  fma2(a1, w[13], O6.y);
            fma2(a2, w[14], O7.x);  fma2(a3, w[15], O7.y);

            // 2-level packed reduce, horizontal add, MUFU tanh
            float2 rr = unpack2(add2(add2(a0, a1), add2(a2, a3)));
            float hval = tanh_approx(rr.x + rr.y);
            hv[q] = hval;

            sh[nbuf][j] = hval;       // publish h_t; bar orders + makes visible
            __syncthreads();
        }
        // batched gmem stream of the 8 h rows (overlaps next prefetch)
#pragma unroll
        for (int q = 0; q < 8; q++) out[(size_t)(t + q) * HD + j] = hv[q];
#pragma unroll
        for (int q = 0; q < 8; q++) xwb[q] = xwn[q] + bj;
    }

    if (has_hn) hn[j] = hv[7];
}

// ---------- launcher ----------
extern "C" void kernel_launch(void* const* d_in, const int* in_sizes, int n_in,
                              void* d_out, int out_size)
{
    (void)n_in;
    const float* input = (const float*)d_in[0];  // [S, 256]
    const float* h0    = (const float*)d_in[1];  // [1, 128]
    const float* Wi    = (const float*)d_in[2];  // [128, 256]
    const float* bi    = (const float*)d_in[3];  // [128]
    const float* Wh    = (const float*)d_in[4];  // [128, 128]
    const float* bh    = (const float*)d_in[5];  // [128]
    float* out = (float*)d_out;

    const int S = in_sizes[0] / DD;
    const int has_hn = (out_size >= S * HD + HD) ? 1 : 0;
    float* hn = out + (size_t)S * HD;

    gemm_xw_kernel<<<(S + 31) / 32, 128>>>(input, Wi, bi, out, S);
    rnn_seq_kernel<<<1, 128>>>(Wh, bh, h0, out, hn, S, has_hn);
}

// round 13
// speedup vs baseline: 1.0736x; 1.0736x over previous
#include <cuda_runtime.h>
#include <cstdint>

typedef unsigned long long ull;

#define HD 128
#define DD 256

// ---------- packed f32x2 helpers (Blackwell sm_100+) ----------
__device__ __forceinline__ void fma2(ull &d, ull a, ull b) {
    asm("fma.rn.f32x2 %0, %1, %2, %0;" : "+l"(d) : "l"(a), "l"(b));
}
__device__ __forceinline__ ull add2(ull a, ull b) {
    ull d; asm("add.rn.f32x2 %0, %1, %2;" : "=l"(d) : "l"(a), "l"(b)); return d;
}
__device__ __forceinline__ float2 unpack2(ull u) {
    float2 r; asm("mov.b64 {%0, %1}, %2;" : "=f"(r.x), "=f"(r.y) : "l"(u)); return r;
}
__device__ __forceinline__ ull pack2(float lo, float hi) {
    ull d; asm("mov.b64 %0, {%1, %2};" : "=l"(d) : "f"(lo), "f"(hi)); return d;
}
__device__ __forceinline__ float tanh_approx(float x) {
    float r; asm("tanh.approx.f32 %0, %1;" : "=f"(r) : "f"(x)); return r;
}

// ---------- Kernel 1: xW = input @ Wi^T + bi, written into out[S,128] ----------
__global__ void __launch_bounds__(128) gemm_xw_kernel(
    const float* __restrict__ X,   // [S, 256]
    const float* __restrict__ Wi,  // [128, 256]
    const float* __restrict__ bi,  // [128]
    float* __restrict__ out, int S)
{
    __shared__ __align__(16) float xs[32][DD];
    const int h  = threadIdx.x;
    const int s0 = blockIdx.x * 32;

    const float4* Xg  = (const float4*)(X + (size_t)s0 * DD);
    float4*       xs4 = (float4*)&xs[0][0];
#pragma unroll
    for (int i = 0; i < 16; i++) xs4[h + 128 * i] = Xg[h + 128 * i];
    __syncthreads();

    float acc[32];
#pragma unroll
    for (int s = 0; s < 32; s++) acc[s] = 0.f;

    const float4* wr = (const float4*)(Wi + h * DD);
#pragma unroll 4
    for (int kk = 0; kk < DD / 4; kk++) {
        float4 wv = wr[kk];
#pragma unroll
        for (int s = 0; s < 32; s++) {
            float4 xv = *(const float4*)&xs[s][kk * 4];
            acc[s] = fmaf(wv.x, xv.x, acc[s]);
            acc[s] = fmaf(wv.y, xv.y, acc[s]);
            acc[s] = fmaf(wv.z, xv.z, acc[s]);
            acc[s] = fmaf(wv.w, xv.w, acc[s]);
        }
    }
    const float b = bi[h];
#pragma unroll
    for (int s = 0; s < 32; s++) out[(size_t)(s0 + s) * HD + h] = acc[s] + b;
}

// ---------- Kernel 2: sequential recurrence ----------
// 128 threads = 4 warps (1/SMSP). Lane j owns output j; full Wh row j in
// registers, PRE-ROTATED so register group g <-> K-group (2*wrp+g)&7.
// R9 structure (best known): pre-bar each warp preloads its OWN 32 h-values
// (STS -> __syncwarp -> LDS; syncwarp REQUIRED, no same-warp STS->LDS fwd).
// R13 change: post-bar order is own-g0 FMAs (register-only; execute during
// barrier drain via BAR.SYNC.DEFER_BLOCKING) -> foreign g2/g3 loads ->
// own-g1 FMAs (cover the foreign LDS latency) -> foreign FMA stream with
// depth-2 lookahead. 4-acc round-robin throughout; MUFU tanh; batched STG.
__global__ void __launch_bounds__(128, 1) rnn_seq_kernel(
    const float* __restrict__ Wh,  // [128, 128]
    const float* __restrict__ bh,  // [128]
    const float* __restrict__ h0,  // [1, 128]
    float* out,                    // [S, 128]: xw in, h out
    float* hn, int S, int has_hn)
{
    __shared__ __align__(16) float sh[2][HD];
    const int j   = threadIdx.x;
    const int wrp = j >> 5;

    // pre-rotated weights: register group g <-> K-group (2*wrp+g)&7
    ull w[64];
#pragma unroll
    for (int g = 0; g < 8; g++) {
        const int kg = (2 * wrp + g) & 7;
        const ulonglong2* wp = (const ulonglong2*)(Wh + j * HD + kg * 16);
#pragma unroll
        for (int u = 0; u < 4; u++) {
            ulonglong2 v = wp[u];
            w[8 * g + 2 * u]     = v.x;
            w[8 * g + 2 * u + 1] = v.y;
        }
    }
    const float bj = bh[j];

    sh[0][j] = h0[j];

    float xwb[8], xwn[8], hv[8];
#pragma unroll
    for (int q = 0; q < 8; q++) xwb[q] = out[q * HD + j] + bj;

    __syncthreads();

    // preload own segment (rotated groups 0,1) of buf 0
    ull own[16];
    {
        const ulonglong2* op = (const ulonglong2*)(&sh[0][wrp * 32]);
#pragma unroll
        for (int u = 0; u < 8; u++) { ulonglong2 v = op[u]; own[2*u] = v.x; own[2*u+1] = v.y; }
    }

    for (int t = 0; t < S; t += 8) {
        // prefetch the next 8 xw rows (consumed next outer iteration)
#pragma unroll
        for (int q = 0; q < 8; q++) {
            int tn = t + 8 + q;
            xwn[q] = (tn < S) ? out[(size_t)tn * HD + j] : 0.f;
        }
#pragma unroll
        for (int q = 0; q < 8; q++) {
            const int buf  = q & 1;        // t % 8 == 0, so step parity == q parity
            const int nbuf = buf ^ 1;
            const float* hb = &sh[buf][0];

            // a0 seeded with (xw + bias); 4-acc round-robin
            ull a0 = pack2(xwb[q], 0.0f);
            ull a1 = 0, a2 = 0, a3 = 0;

            // ---- phase 1: own group 0 (register-only; runs during bar drain)
            fma2(a0, w[0], own[0]);  fma2(a1, w[1], own[1]);
            fma2(a2, w[2], own[2]);  fma2(a3, w[3], own[3]);
            fma2(a0, w[4], own[4]);  fma2(a1, w[5], own[5]);
            fma2(a2, w[6], own[6]);  fma2(a3, w[7], own[7]);

            // ---- phase 2: foreign g2/g3 loads (first shared consumer of bar)
            const ulonglong2* g2p = (const ulonglong2*)(hb + (((2*wrp + 2) & 7) << 4));
            const ulonglong2* g3p = (const ulonglong2*)(hb + (((2*wrp + 3) & 7) << 4));
            ulonglong2 A0 = g2p[0], A1 = g2p[1], A2 = g2p[2], A3 = g2p[3];
            ulonglong2 B0 = g3p[0], B1 = g3p[1], B2 = g3p[2], B3 = g3p[3];

            // ---- phase 3: own group 1 (covers foreign LDS latency)
            fma2(a0, w[ 8], own[ 8]);  fma2(a1, w[ 9], own[ 9]);
            fma2(a2, w[10], own[10]);  fma2(a3, w[11], own[11]);
            fma2(a0, w[12], own[12]);  fma2(a1, w[13], own[13]);
            fma2(a2, w[14], own[14]);  fma2(a3, w[15], own[15]);

            // ---- phase 4: foreign groups 2..7, depth-2 lookahead
#pragma unroll
            for (int g = 2; g < 8; g++) {
                ulonglong2 N0, N1, N2, N3;
                if (g < 6) {
                    const ulonglong2* np = (const ulonglong2*)(hb + (((2*wrp + g + 2) & 7) << 4));
                    N0 = np[0]; N1 = np[1]; N2 = np[2]; N3 = np[3];
                }
                fma2(a0, w[8*g + 0], A0.x);
                fma2(a1, w[8*g + 1], A0.y);
                fma2(a2, w[8*g + 2], A1.x);
                fma2(a3, w[8*g + 3], A1.y);
                fma2(a0, w[8*g + 4], A2.x);
                fma2(a1, w[8*g + 5], A2.y);
                fma2(a2, w[8*g + 6], A3.x);
                fma2(a3, w[8*g + 7], A3.y);
                A0 = B0; A1 = B1; A2 = B2; A3 = B3;
                if (g < 6) { B0 = N0; B1 = N1; B2 = N2; B3 = N3; }
            }
            // 2-level packed reduce, horizontal add, MUFU tanh
            float2 rr = unpack2(add2(add2(a0, a1), add2(a2, a3)));
            float hval = tanh_approx(rr.x + rr.y);
            hv[q] = hval;

            sh[nbuf][j] = hval;       // publish h_t
            __syncwarp();             // REQUIRED: no same-warp STS->LDS fwd (R10)
            // pre-bar preload of OWN segment of the next buffer
            {
                const ulonglong2* op = (const ulonglong2*)(&sh[nbuf][wrp * 32]);
#pragma unroll
                for (int u = 0; u < 8; u++) { ulonglong2 v = op[u]; own[2*u] = v.x; own[2*u+1] = v.y; }
            }
            __syncthreads();
        }
        // batched gmem stream of the 8 h rows (overlaps next prefetch)
#pragma unroll
        for (int q = 0; q < 8; q++) out[(size_t)(t + q) * HD + j] = hv[q];
#pragma unroll
        for (int q = 0; q < 8; q++) xwb[q] = xwn[q] + bj;
    }

    if (has_hn) hn[j] = hv[7];
}

// ---------- launcher ----------
extern "C" void kernel_launch(void* const* d_in, const int* in_sizes, int n_in,
                              void* d_out, int out_size)
{
    (void)n_in;
    const float* input = (const float*)d_in[0];  // [S, 256]
    const float* h0    = (const float*)d_in[1];  // [1, 128]
    const float* Wi    = (const float*)d_in[2];  // [128, 256]
    const float* bi    = (const float*)d_in[3];  // [128]
    const float* Wh    = (const float*)d_in[4];  // [128, 128]
    const float* bh    = (const float*)d_in[5];  // [128]
    float* out = (float*)d_out;

    const int S = in_sizes[0] / DD;
    const int has_hn = (out_size >= S * HD + HD) ? 1 : 0;
    float* hn = out + (size_t)S * HD;

    gemm_xw_kernel<<<(S + 31) / 32, 128>>>(input, Wi, bi, out, S);
    rnn_seq_kernel<<<1, 128>>>(Wh, bh, h0, out, hn, S, has_hn);
}

// round 14
// speedup vs baseline: 1.0747x; 1.0011x over previous
#include <cuda_runtime.h>
#include <cstdint>

typedef unsigned long long ull;

#define HD 128
#define DD 256

// ---------- packed f32x2 helpers (Blackwell sm_100+) ----------
__device__ __forceinline__ void fma2(ull &d, ull a, ull b) {
    asm("fma.rn.f32x2 %0, %1, %2, %0;" : "+l"(d) : "l"(a), "l"(b));
}
__device__ __forceinline__ ull add2(ull a, ull b) {
    ull d; asm("add.rn.f32x2 %0, %1, %2;" : "=l"(d) : "l"(a), "l"(b)); return d;
}
__device__ __forceinline__ float2 unpack2(ull u) {
    float2 r; asm("mov.b64 {%0, %1}, %2;" : "=f"(r.x), "=f"(r.y) : "l"(u)); return r;
}
__device__ __forceinline__ ull pack2(float lo, float hi) {
    ull d; asm("mov.b64 %0, {%1, %2};" : "=l"(d) : "f"(lo), "f"(hi)); return d;
}
__device__ __forceinline__ float tanh_approx(float x) {
    float r; asm("tanh.approx.f32 %0, %1;" : "=f"(r) : "f"(x)); return r;
}

// ---------- Kernel 1: xW = input @ Wi^T + bi, written into out[S,128] ----------
__global__ void __launch_bounds__(128) gemm_xw_kernel(
    const float* __restrict__ X,   // [S, 256]
    const float* __restrict__ Wi,  // [128, 256]
    const float* __restrict__ bi,  // [128]
    float* __restrict__ out, int S)
{
    __shared__ __align__(16) float xs[32][DD];
    const int h  = threadIdx.x;
    const int s0 = blockIdx.x * 32;

    const float4* Xg  = (const float4*)(X + (size_t)s0 * DD);
    float4*       xs4 = (float4*)&xs[0][0];
#pragma unroll
    for (int i = 0; i < 16; i++) xs4[h + 128 * i] = Xg[h + 128 * i];
    __syncthreads();

    float acc[32];
#pragma unroll
    for (int s = 0; s < 32; s++) acc[s] = 0.f;

    const float4* wr = (const float4*)(Wi + h * DD);
#pragma unroll 4
    for (int kk = 0; kk < DD / 4; kk++) {
        float4 wv = wr[kk];
#pragma unroll
        for (int s = 0; s < 32; s++) {
            float4 xv = *(const float4*)&xs[s][kk * 4];
            acc[s] = fmaf(wv.x, xv.x, acc[s]);
            acc[s] = fmaf(wv.y, xv.y, acc[s]);
            acc[s] = fmaf(wv.z, xv.z, acc[s]);
            acc[s] = fmaf(wv.w, xv.w, acc[s]);
        }
    }
    const float b = bi[h];
#pragma unroll
    for (int s = 0; s < 32; s++) out[(size_t)(s0 + s) * HD + h] = acc[s] + b;
}

// ---------- Kernel 2: sequential recurrence (locked R9 design) ----------
// 128 threads = 4 warps (1/SMSP). Lane j owns output j; full Wh row j in
// registers, PRE-ROTATED so register group g <-> K-group (2*wrp+g)&7.
// Pre-barrier, each warp preloads its OWN 32 h-values (STS -> __syncwarp ->
// LDS; syncwarp REQUIRED: sm_100a has no same-warp STS->LDS forwarding,
// proven by R10's 0.19 rel_err) so post-barrier FMA starts from registers;
// foreign groups stream with depth-2 lookahead under the FFMA2 issue.
// 4-accumulator round-robin (R11: 2-chain phases regress); xw+bias seeded
// into a0; single-MUFU tanh (R6/R7: rel_err ~4e-6, contractive recurrence);
// gmem h stores batched outside the inner loop; xw prefetched 8 ahead.
// Measured cycle: bar ~40 + FFMA2 192 (rt-3 banking floor) + tail ~90.
__global__ void __launch_bounds__(128, 1) rnn_seq_kernel(
    const float* __restrict__ Wh,  // [128, 128]
    const float* __restrict__ bh,  // [128]
    const float* __restrict__ h0,  // [1, 128]
    float* out,                    // [S, 128]: xw in, h out
    float* hn, int S, int has_hn)
{
    __shared__ __align__(16) float sh[2][HD];
    const int j   = threadIdx.x;
    const int wrp = j >> 5;

    // pre-rotated weights: register group g <-> K-group (2*wrp+g)&7
    ull w[64];
#pragma unroll
    for (int g = 0; g < 8; g++) {
        const int kg = (2 * wrp + g) & 7;
        const ulonglong2* wp = (const ulonglong2*)(Wh + j * HD + kg * 16);
#pragma unroll
        for (int u = 0; u < 4; u++) {
            ulonglong2 v = wp[u];
            w[8 * g + 2 * u]     = v.x;
            w[8 * g + 2 * u + 1] = v.y;
        }
    }
    const float bj = bh[j];

    sh[0][j] = h0[j];

    float xwb[8], xwn[8], hv[8];
#pragma unroll
    for (int q = 0; q < 8; q++) xwb[q] = out[q * HD + j] + bj;

    __syncthreads();

    // preload own segment (rotated groups 0,1) of buf 0
    ull own[16];
    {
        const ulonglong2* op = (const ulonglong2*)(&sh[0][wrp * 32]);
#pragma unroll
        for (int u = 0; u < 8; u++) { ulonglong2 v = op[u]; own[2*u] = v.x; own[2*u+1] = v.y; }
    }

    for (int t = 0; t < S; t += 8) {
        // prefetch the next 8 xw rows (consumed next outer iteration)
#pragma unroll
        for (int q = 0; q < 8; q++) {
            int tn = t + 8 + q;
            xwn[q] = (tn < S) ? out[(size_t)tn * HD + j] : 0.f;
        }
#pragma unroll
        for (int q = 0; q < 8; q++) {
            const int buf  = q & 1;        // t % 8 == 0, so step parity == q parity
            const int nbuf = buf ^ 1;
            const float* hb = &sh[buf][0];

            // foreign groups, depth-2 lookahead (rotated groups 2..7)
            const ulonglong2* g2p = (const ulonglong2*)(hb + (((2*wrp + 2) & 7) << 4));
            const ulonglong2* g3p = (const ulonglong2*)(hb + (((2*wrp + 3) & 7) << 4));
            ulonglong2 A0 = g2p[0], A1 = g2p[1], A2 = g2p[2], A3 = g2p[3];
            ulonglong2 B0 = g3p[0], B1 = g3p[1], B2 = g3p[2], B3 = g3p[3];

            // a0 seeded with (xw + bias); 4-acc round-robin throughout
            ull a0 = pack2(xwb[q], 0.0f);
            ull a1 = 0, a2 = 0, a3 = 0;

            // own groups first: 16 FFMA2 straight from pre-bar registers
#pragma unroll
            for (int u = 0; u < 4; u++) {
                fma2(a0, w[4*u + 0], own[4*u + 0]);
                fma2(a1, w[4*u + 1], own[4*u + 1]);
                fma2(a2, w[4*u + 2], own[4*u + 2]);
                fma2(a3, w[4*u + 3], own[4*u + 3]);
            }
            // foreign groups 2..7
#pragma unroll
            for (int g = 2; g < 8; g++) {
                ulonglong2 N0, N1, N2, N3;
                if (g < 6) {
                    const ulonglong2* np = (const ulonglong2*)(hb + (((2*wrp + g + 2) & 7) << 4));
                    N0 = np[0]; N1 = np[1]; N2 = np[2]; N3 = np[3];
                }
                fma2(a0, w[8*g + 0], A0.x);
                fma2(a1, w[8*g + 1], A0.y);
                fma2(a2, w[8*g + 2], A1.x);
                fma2(a3, w[8*g + 3], A1.y);
                fma2(a0, w[8*g + 4], A2.x);
                fma2(a1, w[8*g + 5], A2.y);
                fma2(a2, w[8*g + 6], A3.x);
                fma2(a3, w[8*g + 7], A3.y);
                A0 = B0; A1 = B1; A2 = B2; A3 = B3;
                if (g < 6) { B0 = N0; B1 = N1; B2 = N2; B3 = N3; }
            }
            // 2-level packed reduce, horizontal add, MUFU tanh
            float2 rr = unpack2(add2(add2(a0, a1), add2(a2, a3)));
            float hval = tanh_approx(rr.x + rr.y);
            hv[q] = hval;

            sh[nbuf][j] = hval;       // publish h_t
            __syncwarp();             // REQUIRED: no same-warp STS->LDS fwd (R10)
            // pre-bar preload of OWN segment of the next buffer
            {
                const ulonglong2* op = (const ulonglong2*)(&sh[nbuf][wrp * 32]);
#pragma unroll
                for (int u = 0; u < 8; u++) { ulonglong2 v = op[u]; own[2*u] = v.x; own[2*u+1] = v.y; }
            }
            __syncthreads();
        }
        // batched gmem stream of the 8 h rows (overlaps next prefetch)
#pragma unroll
        for (int q = 0; q < 8; q++) out[(size_t)(t + q) * HD + j] = hv[q];
#pragma unroll
        for (int q = 0; q < 8; q++) xwb[q] = xwn[q] + bj;
    }

    if (has_hn) hn[j] = hv[7];
}

// ---------- launcher ----------
extern "C" void kernel_launch(void* const* d_in, const int* in_sizes, int n_in,
                              void* d_out, int out_size)
{
    (void)n_in;
    const float* input = (const float*)d_in[0];  // [S, 256]
    const float* h0    = (const float*)d_in[1];  // [1, 128]
    const float* Wi    = (const float*)d_in[2];  // [128, 256]
    const float* bi    = (const float*)d_in[3];  // [128]
    const float* Wh    = (const float*)d_in[4];  // [128, 128]
    const float* bh    = (const float*)d_in[5];  // [128]
    float* out = (float*)d_out;

    const int S = in_sizes[0] / DD;
    const int has_hn = (out_size >= S * HD + HD) ? 1 : 0;
    float* hn = out + (size_t)S * HD;

    gemm_xw_kernel<<<(S + 31) / 32, 128>>>(input, Wi, bi, out, S);
    rnn_seq_kernel<<<1, 128>>>(Wh, bh, h0, out, hn, S, has_hn);
}